// round 14
// baseline (speedup 1.0000x reference)
#include <cuda_runtime.h>
#include <math_constants.h>

// Exact 8-NN IDW flow interpolation: uniform grid + expanding shells.
// Phase A: TWO threads per query (lane-pair splits candidate rows), box l<=1
// then shell l=2, batch-4 scans. Phase B: warp-per-query tail.
// Inputs: query_points [N,3] f32, ref_points [M,3] f32, ref_flow [M,3] f32 ; out [N,3] f32

#define NMAX  32768
#define MMAX  16384
#define KNN   8
#define G     32
#define NCELL (G * G * G)
#define CHUNK 512
#define NCHUNK (NCELL / CHUNK)   // 64

__device__ float4 g_pts[MMAX];
__device__ int    g_sid[MMAX];
__device__ int    g_cstart[NCELL + 1];
__device__ int    g_ccnt[NCELL];
__device__ int    g_ccur[NCELL];
__device__ int    g_cellof[MMAX];
__device__ int    g_qcnt[NCELL];
__device__ int    g_qcur[NCELL];
__device__ int    g_qcell[NMAX];
__device__ float4 g_qs[NMAX];          // cell-sorted query coords (x,y,z,|q|^2)
__device__ int    g_qid[NMAX];         // sorted slot -> original query index
__device__ int    g_hard[NMAX];        // sorted slots of unresolved queries
__device__ int    g_hardcnt;
__device__ float  g_bb[8];             // [0..2]=min, [3..5]=1/h, [6]=hmin
__device__ int    g_bsum[2 * NCHUNK];
__device__ unsigned g_bbmin[3], g_bbmax[3];
__device__ int    g_bbdone;

__device__ __forceinline__ unsigned f2key(float f) {
    unsigned b = __float_as_uint(f);
    return b ^ ((b & 0x80000000u) ? 0xFFFFFFFFu : 0x80000000u);
}
__device__ __forceinline__ float key2f(unsigned k) {
    unsigned b = (k & 0x80000000u) ? (k ^ 0x80000000u) : ~k;
    return __uint_as_float(b);
}

__global__ void init_kernel() {
    int i = blockIdx.x * blockDim.x + threadIdx.x;
    if (i < NCELL) { g_ccnt[i] = 0; g_qcnt[i] = 0; }
    if (i == 0) {
        g_hardcnt = 0;
        g_bbdone = 0;
#pragma unroll
        for (int a = 0; a < 3; ++a) { g_bbmin[a] = 0xFFFFFFFFu; g_bbmax[a] = 0u; }
    }
}

__global__ void __launch_bounds__(256) bbox_kernel(const float* __restrict__ ref, int M) {
    __shared__ float smn[3][8], smx[3][8];
    int t = threadIdx.x, lane = t & 31, wid = t >> 5;
    float mn[3] = {CUDART_INF_F, CUDART_INF_F, CUDART_INF_F};
    float mx[3] = {-CUDART_INF_F, -CUDART_INF_F, -CUDART_INF_F};
    for (int i = blockIdx.x * blockDim.x + t; i < M; i += gridDim.x * blockDim.x) {
#pragma unroll
        for (int a = 0; a < 3; ++a) {
            float v = ref[3 * i + a];
            mn[a] = fminf(mn[a], v);
            mx[a] = fmaxf(mx[a], v);
        }
    }
#pragma unroll
    for (int off = 16; off > 0; off >>= 1) {
#pragma unroll
        for (int a = 0; a < 3; ++a) {
            mn[a] = fminf(mn[a], __shfl_xor_sync(0xffffffffu, mn[a], off));
            mx[a] = fmaxf(mx[a], __shfl_xor_sync(0xffffffffu, mx[a], off));
        }
    }
    if (lane == 0) {
#pragma unroll
        for (int a = 0; a < 3; ++a) { smn[a][wid] = mn[a]; smx[a][wid] = mx[a]; }
    }
    __syncthreads();
    if (t == 0) {
#pragma unroll
        for (int a = 0; a < 3; ++a) {
            float bmn = smn[a][0], bmx = smx[a][0];
            for (int w = 1; w < 8; ++w) {
                bmn = fminf(bmn, smn[a][w]);
                bmx = fmaxf(bmx, smx[a][w]);
            }
            atomicMin(&g_bbmin[a], f2key(bmn));
            atomicMax(&g_bbmax[a], f2key(bmx));
        }
        __threadfence();
        int done = atomicAdd(&g_bbdone, 1);
        if (done == gridDim.x - 1) {
            float hmin = CUDART_INF_F;
#pragma unroll
            for (int a = 0; a < 3; ++a) {
                float lo = key2f(g_bbmin[a]) - 1e-4f;
                float hi = key2f(g_bbmax[a]) + 1e-4f;
                float h = fmaxf((hi - lo) / (float)G, 1e-6f);
                g_bb[a] = lo;
                g_bb[3 + a] = 1.0f / h;
                hmin = fminf(hmin, h);
            }
            g_bb[6] = hmin;
        }
    }
}

__device__ __forceinline__ int cell_of(float x, float y, float z) {
    int cx = (int)((x - g_bb[0]) * g_bb[3]);
    int cy = (int)((y - g_bb[1]) * g_bb[4]);
    int cz = (int)((z - g_bb[2]) * g_bb[5]);
    cx = min(G - 1, max(0, cx));
    cy = min(G - 1, max(0, cy));
    cz = min(G - 1, max(0, cz));
    return (cz * G + cy) * G + cx;
}

__global__ void hist_kernel(const float* __restrict__ ref,
                            const float* __restrict__ qp, int M, int N) {
    int i = blockIdx.x * blockDim.x + threadIdx.x;
    if (i < M) {
        int c = cell_of(ref[3 * i + 0], ref[3 * i + 1], ref[3 * i + 2]);
        g_cellof[i] = c;
        atomicAdd(&g_ccnt[c], 1);
    } else if (i < M + N) {
        int j = i - M;
        int c = cell_of(qp[3 * j + 0], qp[3 * j + 1], qp[3 * j + 2]);
        g_qcell[j] = c;
        atomicAdd(&g_qcnt[c], 1);
    }
}

__global__ void __launch_bounds__(256) scan1_kernel() {
    __shared__ int wsum[8];
    int b = blockIdx.x;
    const int* cnt = (b < NCHUNK) ? g_ccnt : g_qcnt;
    int c0 = (b & (NCHUNK - 1)) * CHUNK;
    int t = threadIdx.x, lane = t & 31, wid = t >> 5;
    int2 v = *(const int2*)&cnt[c0 + 2 * t];
    int s = v.x + v.y;
#pragma unroll
    for (int off = 16; off > 0; off >>= 1)
        s += __shfl_xor_sync(0xffffffffu, s, off);
    if (lane == 0) wsum[wid] = s;
    __syncthreads();
    if (t == 0) {
        int tot = 0;
#pragma unroll
        for (int w = 0; w < 8; ++w) tot += wsum[w];
        g_bsum[b] = tot;
    }
}

__global__ void __launch_bounds__(256) scan2_kernel(int M, int N) {
    __shared__ int wsum[8];
    __shared__ int chunk_off;
    int b = blockIdx.x;
    bool isq = (b >= NCHUNK);
    const int* cnt = isq ? g_qcnt : g_ccnt;
    int t = threadIdx.x, lane = t & 31, wid = t >> 5;

    if (wid == 0) {
        int base = (isq ? NCHUNK : 0);
        int v0 = g_bsum[base + 2 * lane];
        int v1 = g_bsum[base + 2 * lane + 1];
        int s = v0 + v1;
        int inc = s;
#pragma unroll
        for (int off = 1; off < 32; off <<= 1) {
            int u = __shfl_up_sync(0xffffffffu, inc, off);
            if (lane >= off) inc += u;
        }
        int ex = inc - s;
        int myc = b & (NCHUNK - 1);
        int want0 = myc >> 1;
        int sel = __shfl_sync(0xffffffffu, ex, want0);
        int selv0 = __shfl_sync(0xffffffffu, v0, want0);
        if (lane == 0) chunk_off = (myc & 1) ? (sel + selv0) : sel;
    }
    __syncthreads();

    const int c0 = (b & (NCHUNK - 1)) * CHUNK;
    int2 v = *(const int2*)&cnt[c0 + 2 * t];
    int s = v.x + v.y;
    int inc = s;
#pragma unroll
    for (int off = 1; off < 32; off <<= 1) {
        int u = __shfl_up_sync(0xffffffffu, inc, off);
        if (lane >= off) inc += u;
    }
    if (lane == 31) wsum[wid] = inc;
    __syncthreads();
    if (wid == 0 && lane < 8) {
        int w = wsum[lane];
#pragma unroll
        for (int off = 1; off < 8; off <<= 1) {
            int u = __shfl_up_sync(0xffu, w, off);
            if (lane >= off) w += u;
        }
        wsum[lane] = w;
    }
    __syncthreads();
    int ex = inc - s + (wid ? wsum[wid - 1] : 0) + chunk_off;
    int2 st = make_int2(ex, ex + v.x);
    if (isq) {
        *(int2*)&g_qcur[c0 + 2 * t] = st;
    } else {
        *(int2*)&g_cstart[c0 + 2 * t] = st;
        *(int2*)&g_ccur[c0 + 2 * t] = st;
    }
    if (!isq && b == 0 && t == 0) g_cstart[NCELL] = M;
}

__global__ void scatter_kernel(const float* __restrict__ ref,
                               const float* __restrict__ qp, int M, int N) {
    int i = blockIdx.x * blockDim.x + threadIdx.x;
    if (i < M) {
        float x = ref[3 * i + 0];
        float y = ref[3 * i + 1];
        float z = ref[3 * i + 2];
        int c = g_cellof[i];
        int p = atomicAdd(&g_ccur[c], 1);
        g_pts[p] = make_float4(x, y, z, fmaf(x, x, fmaf(y, y, z * z)));
        g_sid[p] = i;
    } else if (i < M + N) {
        int j = i - M;
        float x = qp[3 * j + 0];
        float y = qp[3 * j + 1];
        float z = qp[3 * j + 2];
        int c = g_qcell[j];
        int p = atomicAdd(&g_qcur[c], 1);
        g_qs[p] = make_float4(x, y, z, fmaf(x, x, fmaf(y, y, z * z)));
        g_qid[p] = j;
    }
}

__device__ __forceinline__ void idw_store(
    const float* __restrict__ flow, float* __restrict__ out,
    int qi, float q2, const float* bd, const int* bi)
{
    float wsum = 0.f, ox = 0.f, oy = 0.f, oz = 0.f;
#pragma unroll
    for (int k = 0; k < KNN; ++k) {
        float d2 = fmaxf(q2 + bd[k], 0.0f);
        float w = 1.0f / (d2 + 1e-8f);
        int id = bi[k];
        ox = fmaf(w, flow[3 * id + 0], ox);
        oy = fmaf(w, flow[3 * id + 1], oy);
        oz = fmaf(w, flow[3 * id + 2], oz);
        wsum += w;
    }
    float inv = 1.0f / wsum;
    out[3 * qi + 0] = ox * inv;
    out[3 * qi + 1] = oy * inv;
    out[3 * qi + 2] = oz * inv;
}

// Phase A: two threads per query; lane pair (2t, 2t+1) splits candidate rows by
// parity (disjoint sets). All pair shfls use the PAIR MASK (valid under pair-
// uniform divergence); final merge snapshots partner entries before inserting.
__global__ void __launch_bounds__(128) knn_easy_kernel(
    const float* __restrict__ flow,
    float* __restrict__ out, int N)
{
    int tid = blockIdx.x * blockDim.x + threadIdx.x;
    int tq = tid >> 1;          // query slot (cell-sorted)
    int par = tid & 1;          // which half of the rows this thread scans
    if (tq >= N) return;

    const int lane = threadIdx.x & 31;
    const unsigned pmask = 3u << (lane & 30);   // this lane pair only

    float4 qv = g_qs[tq];
    const float nqx = -2.0f * qv.x;
    const float nqy = -2.0f * qv.y;
    const float nqz = -2.0f * qv.z;
    const float q2 = qv.w;
    const float hmin = g_bb[6];

    int cx = (int)((qv.x - g_bb[0]) * g_bb[3]);
    int cy = (int)((qv.y - g_bb[1]) * g_bb[4]);
    int cz = (int)((qv.z - g_bb[2]) * g_bb[5]);
    cx = min(G - 1, max(0, cx));
    cy = min(G - 1, max(0, cy));
    cz = min(G - 1, max(0, cz));

    float bd[KNN];
    int   bi[KNN];
#pragma unroll
    for (int k = 0; k < KNN; ++k) { bd[k] = CUDART_INF_F; bi[k] = 0; }

    auto insv = [&](float sc, int id) {
        if (sc < bd[KNN - 1]) {
            bd[KNN - 1] = sc;
            bi[KNN - 1] = id;
#pragma unroll
            for (int k = KNN - 1; k > 0; --k) {
                if (bd[k] < bd[k - 1]) {
                    float td = bd[k]; bd[k] = bd[k - 1]; bd[k - 1] = td;
                    int   ti = bi[k]; bi[k] = bi[k - 1]; bi[k - 1] = ti;
                }
            }
        }
    };
    auto ins = [&](float sc, int p) { insv(sc, g_sid[p]); };

    int rowctr = 0;   // identical call sequence on both lanes -> same numbering
    auto do_row = [&](int z, int y, int x0, int x1) {
        if ((rowctr++ & 1) != par) return;
        if ((unsigned)z >= G || (unsigned)y >= G) return;
        x0 = max(x0, 0);
        x1 = min(x1, G - 1);
        if (x0 > x1) return;
        int rb = (z * G + y) * G;
        int p = g_cstart[rb + x0];
        int e = g_cstart[rb + x1 + 1];
        for (; p + 4 <= e; p += 4) {
            float4 r0 = g_pts[p + 0];
            float4 r1 = g_pts[p + 1];
            float4 r2 = g_pts[p + 2];
            float4 r3 = g_pts[p + 3];
            float s0 = fmaf(r0.x, nqx, fmaf(r0.y, nqy, fmaf(r0.z, nqz, r0.w)));
            float s1 = fmaf(r1.x, nqx, fmaf(r1.y, nqy, fmaf(r1.z, nqz, r1.w)));
            float s2 = fmaf(r2.x, nqx, fmaf(r2.y, nqy, fmaf(r2.z, nqz, r2.w)));
            float s3 = fmaf(r3.x, nqx, fmaf(r3.y, nqy, fmaf(r3.z, nqz, r3.w)));
            float m = fminf(fminf(s0, s1), fminf(s2, s3));
            if (m < bd[KNN - 1]) {
                ins(s0, p); ins(s1, p + 1); ins(s2, p + 2); ins(s3, p + 3);
            }
        }
        for (; p < e; ++p) {
            float4 r = g_pts[p];
            float sc = fmaf(r.x, nqx, fmaf(r.y, nqy, fmaf(r.z, nqz, r.w)));
            ins(sc, p);
        }
    };

    // Box l<=1 as 9 rows, split by parity across the lane pair.
    for (int dz = -1; dz <= 1; ++dz)
        for (int dy = -1; dy <= 1; ++dy)
            do_row(cz + dz, cy + dy, cx - 1, cx + 1);

    // Conservative pair-kth: union-8th <= min(lane 8ths), so this stop is safe.
    float kmin = fminf(bd[KNN - 1], __shfl_xor_sync(pmask, bd[KNN - 1], 1));
    bool done = (q2 + kmin < hmin * hmin - 0.05f);
    if (!done) {
        // Shell l=2, split by parity.
        for (int dy = -2; dy <= 2; ++dy) {
            do_row(cz - 2, cy + dy, cx - 2, cx + 2);
            do_row(cz + 2, cy + dy, cx - 2, cx + 2);
        }
        for (int dz = -1; dz <= 1; ++dz) {
            do_row(cz + dz, cy - 2, cx - 2, cx + 2);
            do_row(cz + dz, cy + 2, cx - 2, cx + 2);
            for (int dy = -1; dy <= 1; ++dy) {
                do_row(cz + dz, cy + dy, cx - 2, cx - 2);
                do_row(cz + dz, cy + dy, cx + 2, cx + 2);
            }
        }
        kmin = fminf(bd[KNN - 1], __shfl_xor_sync(pmask, bd[KNN - 1], 1));
        float bound = 2.0f * hmin;
        done = (q2 + kmin < bound * bound - 0.05f);
    }

    if (done) {
        // Exact final merge: SNAPSHOT the partner's 8 entries first (shfl reads
        // its un-mutated list), then insert. Disjoint sets -> no duplicates.
        float od[KNN];
        int   oi[KNN];
#pragma unroll
        for (int k = 0; k < KNN; ++k) {
            od[k] = __shfl_xor_sync(pmask, bd[k], 1);
            oi[k] = __shfl_xor_sync(pmask, bi[k], 1);
        }
#pragma unroll
        for (int k = 0; k < KNN; ++k) insv(od[k], oi[k]);
        if (par == 0) idw_store(flow, out, g_qid[tq], q2, bd, bi);
    } else {
        if (par == 0) {
            int slot = atomicAdd(&g_hardcnt, 1);
            g_hard[slot] = tq;
        }
    }
}

// Phase B: one warp per hard query; lanes split shell rows; per-shell exact merge.
__global__ void __launch_bounds__(256) knn_hard_kernel(
    const float* __restrict__ flow,
    float* __restrict__ out)
{
    __shared__ float sdist[8][32 * KNN];
    __shared__ int   sidx[8][32 * KNN];

    int lane = threadIdx.x & 31;
    int wslot = threadIdx.x >> 5;
    int wgid = (blockIdx.x * blockDim.x + threadIdx.x) >> 5;
    int nwarps = (gridDim.x * blockDim.x) >> 5;
    int hcnt = g_hardcnt;
    const float hmin = g_bb[6];

    for (int h = wgid; h < hcnt; h += nwarps) {
        int tq = g_hard[h];
        float4 qv = g_qs[tq];
        const float nqx = -2.0f * qv.x;
        const float nqy = -2.0f * qv.y;
        const float nqz = -2.0f * qv.z;
        const float q2 = qv.w;

        int cx = (int)((qv.x - g_bb[0]) * g_bb[3]);
        int cy = (int)((qv.y - g_bb[1]) * g_bb[4]);
        int cz = (int)((qv.z - g_bb[2]) * g_bb[5]);
        cx = min(G - 1, max(0, cx));
        cy = min(G - 1, max(0, cy));
        cz = min(G - 1, max(0, cz));

        float bd[KNN];
        int   bi[KNN];
#pragma unroll
        for (int k = 0; k < KNN; ++k) { bd[k] = CUDART_INF_F; bi[k] = 0; }

        auto ins = [&](float sc, int p) {
            if (sc < bd[KNN - 1]) {
                bd[KNN - 1] = sc;
                bi[KNN - 1] = g_sid[p];
#pragma unroll
                for (int k = KNN - 1; k > 0; --k) {
                    if (bd[k] < bd[k - 1]) {
                        float td = bd[k]; bd[k] = bd[k - 1]; bd[k - 1] = td;
                        int   ti = bi[k]; bi[k] = bi[k - 1]; bi[k - 1] = ti;
                    }
                }
            }
        };

        auto scan_run = [&](int z, int y, int x0, int x1) {
            if ((unsigned)z >= G || (unsigned)y >= G) return;
            x0 = max(x0, 0);
            x1 = min(x1, G - 1);
            if (x0 > x1) return;
            int rb = (z * G + y) * G;
            int p = g_cstart[rb + x0];
            int e = g_cstart[rb + x1 + 1];
            for (; p + 4 <= e; p += 4) {
                float4 r0 = g_pts[p + 0];
                float4 r1 = g_pts[p + 1];
                float4 r2 = g_pts[p + 2];
                float4 r3 = g_pts[p + 3];
                float s0 = fmaf(r0.x, nqx, fmaf(r0.y, nqy, fmaf(r0.z, nqz, r0.w)));
                float s1 = fmaf(r1.x, nqx, fmaf(r1.y, nqy, fmaf(r1.z, nqz, r1.w)));
                float s2 = fmaf(r2.x, nqx, fmaf(r2.y, nqy, fmaf(r2.z, nqz, r2.w)));
                float s3 = fmaf(r3.x, nqx, fmaf(r3.y, nqy, fmaf(r3.z, nqz, r3.w)));
                float m = fminf(fminf(s0, s1), fminf(s2, s3));
                if (m < bd[KNN - 1]) {
                    ins(s0, p); ins(s1, p + 1); ins(s2, p + 2); ins(s3, p + 3);
                }
            }
            for (; p < e; ++p) {
                float4 r = g_pts[p];
                float sc = fmaf(r.x, nqx, fmaf(r.y, nqy, fmaf(r.z, nqz, r.w)));
                ins(sc, p);
            }
        };

        float md[KNN];
        int   mi[KNN];
#pragma unroll
        for (int k = 0; k < KNN; ++k) { md[k] = CUDART_INF_F; mi[k] = 0; }

        for (int l = 0; l < G; ++l) {
            int side = 2 * l + 1;
            int pairs = side * side;
            for (int pr = lane; pr < pairs; pr += 32) {
                int dz = pr / side - l;
                int dy = pr % side - l;
                int z = cz + dz, y = cy + dy;
                if (abs(dz) == l || abs(dy) == l) {
                    scan_run(z, y, cx - l, cx + l);
                } else {
                    scan_run(z, y, cx - l, cx - l);
                    scan_run(z, y, cx + l, cx + l);
                }
            }
            __syncwarp();
#pragma unroll
            for (int k = 0; k < KNN; ++k) {
                sdist[wslot][lane * KNN + k] = bd[k];
                sidx[wslot][lane * KNN + k] = bi[k];
            }
            __syncwarp();
            float kth;
            if (lane == 0) {
#pragma unroll
                for (int k = 0; k < KNN; ++k) { md[k] = CUDART_INF_F; mi[k] = 0; }
                for (int e = 0; e < 32 * KNN; ++e) {
                    float v = sdist[wslot][e];
                    if (v < md[KNN - 1]) {
                        md[KNN - 1] = v;
                        mi[KNN - 1] = sidx[wslot][e];
#pragma unroll
                        for (int k = KNN - 1; k > 0; --k) {
                            if (md[k] < md[k - 1]) {
                                float td = md[k]; md[k] = md[k - 1]; md[k - 1] = td;
                                int   ti = mi[k]; mi[k] = mi[k - 1]; mi[k - 1] = ti;
                            }
                        }
                    }
                }
                kth = md[KNN - 1];
            }
            kth = __shfl_sync(0xffffffffu, kth, 0);
            float bound = (float)l * hmin;
            if (q2 + kth < bound * bound - 0.05f) break;
        }

        if (lane == 0) {
            idw_store(flow, out, g_qid[tq], q2, md, mi);
        }
        __syncwarp();
    }
}

extern "C" void kernel_launch(void* const* d_in, const int* in_sizes, int n_in,
                              void* d_out, int out_size) {
    const float* q = (const float*)d_in[0];
    const float* r = (const float*)d_in[1];
    const float* f = (const float*)d_in[2];
    int N = in_sizes[0] / 3;
    int M = in_sizes[1] / 3;
    if (M > MMAX) M = MMAX;
    if (N > NMAX) N = NMAX;

    init_kernel<<<NCELL / 256, 256>>>();
    bbox_kernel<<<64, 256>>>(r, M);
    hist_kernel<<<(M + N + 255) / 256, 256>>>(r, q, M, N);
    scan1_kernel<<<2 * NCHUNK, 256>>>();
    scan2_kernel<<<2 * NCHUNK, 256>>>(M, N);
    scatter_kernel<<<(M + N + 255) / 256, 256>>>(r, q, M, N);
    knn_easy_kernel<<<(2 * N + 127) / 128, 128>>>(f, (float*)d_out, N);
    knn_hard_kernel<<<128, 256>>>(f, (float*)d_out);
}

// round 15
// speedup vs baseline: 1.0059x; 1.0059x over previous
#include <cuda_runtime.h>
#include <math_constants.h>

// Exact 8-NN IDW flow interpolation: uniform grid + expanding shells.
// Phase A: per-thread; box l<=1 then shell l=2; batch-4 scans; bi[] holds grid
// POSITIONS (flow pre-gathered into grid order -> no sid indirection).
// Phase B: warp-per-query tail with shfl-min stop bound + single final merge.
// Inputs: query_points [N,3] f32, ref_points [M,3] f32, ref_flow [M,3] f32 ; out [N,3] f32

#define NMAX  32768
#define MMAX  16384
#define KNN   8
#define G     32
#define NCELL (G * G * G)
#define CHUNK 512
#define NCHUNK (NCELL / CHUNK)   // 64

__device__ float4 g_pts[MMAX];         // grid-sorted refs: (x, y, z, |r|^2)
__device__ float4 g_flw[MMAX];         // grid-sorted flow:  (fx, fy, fz, 0)
__device__ int    g_cstart[NCELL + 1];
__device__ int    g_ccnt[NCELL];
__device__ int    g_ccur[NCELL];
__device__ int    g_cellof[MMAX];
__device__ int    g_qcnt[NCELL];
__device__ int    g_qcur[NCELL];
__device__ int    g_qcell[NMAX];
__device__ float4 g_qs[NMAX];          // cell-sorted query coords (x,y,z,|q|^2)
__device__ int    g_qid[NMAX];         // sorted slot -> original query index
__device__ int    g_hard[NMAX];        // sorted slots of unresolved queries
__device__ int    g_hardcnt;
__device__ float  g_bb[8];             // [0..2]=min, [3..5]=1/h, [6]=hmin
__device__ int    g_bsum[2 * NCHUNK];
__device__ unsigned g_bbmin[3], g_bbmax[3];
__device__ int    g_bbdone;

__device__ __forceinline__ unsigned f2key(float f) {
    unsigned b = __float_as_uint(f);
    return b ^ ((b & 0x80000000u) ? 0xFFFFFFFFu : 0x80000000u);
}
__device__ __forceinline__ float key2f(unsigned k) {
    unsigned b = (k & 0x80000000u) ? (k ^ 0x80000000u) : ~k;
    return __uint_as_float(b);
}

__global__ void init_kernel() {
    int i = blockIdx.x * blockDim.x + threadIdx.x;
    if (i < NCELL) { g_ccnt[i] = 0; g_qcnt[i] = 0; }
    if (i == 0) {
        g_hardcnt = 0;
        g_bbdone = 0;
#pragma unroll
        for (int a = 0; a < 3; ++a) { g_bbmin[a] = 0xFFFFFFFFu; g_bbmax[a] = 0u; }
    }
}

__global__ void __launch_bounds__(256) bbox_kernel(const float* __restrict__ ref, int M) {
    __shared__ float smn[3][8], smx[3][8];
    int t = threadIdx.x, lane = t & 31, wid = t >> 5;
    float mn[3] = {CUDART_INF_F, CUDART_INF_F, CUDART_INF_F};
    float mx[3] = {-CUDART_INF_F, -CUDART_INF_F, -CUDART_INF_F};
    for (int i = blockIdx.x * blockDim.x + t; i < M; i += gridDim.x * blockDim.x) {
#pragma unroll
        for (int a = 0; a < 3; ++a) {
            float v = ref[3 * i + a];
            mn[a] = fminf(mn[a], v);
            mx[a] = fmaxf(mx[a], v);
        }
    }
#pragma unroll
    for (int off = 16; off > 0; off >>= 1) {
#pragma unroll
        for (int a = 0; a < 3; ++a) {
            mn[a] = fminf(mn[a], __shfl_xor_sync(0xffffffffu, mn[a], off));
            mx[a] = fmaxf(mx[a], __shfl_xor_sync(0xffffffffu, mx[a], off));
        }
    }
    if (lane == 0) {
#pragma unroll
        for (int a = 0; a < 3; ++a) { smn[a][wid] = mn[a]; smx[a][wid] = mx[a]; }
    }
    __syncthreads();
    if (t == 0) {
#pragma unroll
        for (int a = 0; a < 3; ++a) {
            float bmn = smn[a][0], bmx = smx[a][0];
            for (int w = 1; w < 8; ++w) {
                bmn = fminf(bmn, smn[a][w]);
                bmx = fmaxf(bmx, smx[a][w]);
            }
            atomicMin(&g_bbmin[a], f2key(bmn));
            atomicMax(&g_bbmax[a], f2key(bmx));
        }
        __threadfence();
        int done = atomicAdd(&g_bbdone, 1);
        if (done == gridDim.x - 1) {
            float hmin = CUDART_INF_F;
#pragma unroll
            for (int a = 0; a < 3; ++a) {
                float lo = key2f(g_bbmin[a]) - 1e-4f;
                float hi = key2f(g_bbmax[a]) + 1e-4f;
                float h = fmaxf((hi - lo) / (float)G, 1e-6f);
                g_bb[a] = lo;
                g_bb[3 + a] = 1.0f / h;
                hmin = fminf(hmin, h);
            }
            g_bb[6] = hmin;
        }
    }
}

__device__ __forceinline__ int cell_of(float x, float y, float z) {
    int cx = (int)((x - g_bb[0]) * g_bb[3]);
    int cy = (int)((y - g_bb[1]) * g_bb[4]);
    int cz = (int)((z - g_bb[2]) * g_bb[5]);
    cx = min(G - 1, max(0, cx));
    cy = min(G - 1, max(0, cy));
    cz = min(G - 1, max(0, cz));
    return (cz * G + cy) * G + cx;
}

__global__ void hist_kernel(const float* __restrict__ ref,
                            const float* __restrict__ qp, int M, int N) {
    int i = blockIdx.x * blockDim.x + threadIdx.x;
    if (i < M) {
        int c = cell_of(ref[3 * i + 0], ref[3 * i + 1], ref[3 * i + 2]);
        g_cellof[i] = c;
        atomicAdd(&g_ccnt[c], 1);
    } else if (i < M + N) {
        int j = i - M;
        int c = cell_of(qp[3 * j + 0], qp[3 * j + 1], qp[3 * j + 2]);
        g_qcell[j] = c;
        atomicAdd(&g_qcnt[c], 1);
    }
}

__global__ void __launch_bounds__(256) scan1_kernel() {
    __shared__ int wsum[8];
    int b = blockIdx.x;
    const int* cnt = (b < NCHUNK) ? g_ccnt : g_qcnt;
    int c0 = (b & (NCHUNK - 1)) * CHUNK;
    int t = threadIdx.x, lane = t & 31, wid = t >> 5;
    int2 v = *(const int2*)&cnt[c0 + 2 * t];
    int s = v.x + v.y;
#pragma unroll
    for (int off = 16; off > 0; off >>= 1)
        s += __shfl_xor_sync(0xffffffffu, s, off);
    if (lane == 0) wsum[wid] = s;
    __syncthreads();
    if (t == 0) {
        int tot = 0;
#pragma unroll
        for (int w = 0; w < 8; ++w) tot += wsum[w];
        g_bsum[b] = tot;
    }
}

__global__ void __launch_bounds__(256) scan2_kernel(int M, int N) {
    __shared__ int wsum[8];
    __shared__ int chunk_off;
    int b = blockIdx.x;
    bool isq = (b >= NCHUNK);
    const int* cnt = isq ? g_qcnt : g_ccnt;
    int t = threadIdx.x, lane = t & 31, wid = t >> 5;

    if (wid == 0) {
        int base = (isq ? NCHUNK : 0);
        int v0 = g_bsum[base + 2 * lane];
        int v1 = g_bsum[base + 2 * lane + 1];
        int s = v0 + v1;
        int inc = s;
#pragma unroll
        for (int off = 1; off < 32; off <<= 1) {
            int u = __shfl_up_sync(0xffffffffu, inc, off);
            if (lane >= off) inc += u;
        }
        int ex = inc - s;
        int myc = b & (NCHUNK - 1);
        int want0 = myc >> 1;
        int sel = __shfl_sync(0xffffffffu, ex, want0);
        int selv0 = __shfl_sync(0xffffffffu, v0, want0);
        if (lane == 0) chunk_off = (myc & 1) ? (sel + selv0) : sel;
    }
    __syncthreads();

    const int c0 = (b & (NCHUNK - 1)) * CHUNK;
    int2 v = *(const int2*)&cnt[c0 + 2 * t];
    int s = v.x + v.y;
    int inc = s;
#pragma unroll
    for (int off = 1; off < 32; off <<= 1) {
        int u = __shfl_up_sync(0xffffffffu, inc, off);
        if (lane >= off) inc += u;
    }
    if (lane == 31) wsum[wid] = inc;
    __syncthreads();
    if (wid == 0 && lane < 8) {
        int w = wsum[lane];
#pragma unroll
        for (int off = 1; off < 8; off <<= 1) {
            int u = __shfl_up_sync(0xffu, w, off);
            if (lane >= off) w += u;
        }
        wsum[lane] = w;
    }
    __syncthreads();
    int ex = inc - s + (wid ? wsum[wid - 1] : 0) + chunk_off;
    int2 st = make_int2(ex, ex + v.x);
    if (isq) {
        *(int2*)&g_qcur[c0 + 2 * t] = st;
    } else {
        *(int2*)&g_cstart[c0 + 2 * t] = st;
        *(int2*)&g_ccur[c0 + 2 * t] = st;
    }
    if (!isq && b == 0 && t == 0) g_cstart[NCELL] = M;
}

__global__ void scatter_kernel(const float* __restrict__ ref,
                               const float* __restrict__ qp,
                               const float* __restrict__ flw, int M, int N) {
    int i = blockIdx.x * blockDim.x + threadIdx.x;
    if (i < M) {
        float x = ref[3 * i + 0];
        float y = ref[3 * i + 1];
        float z = ref[3 * i + 2];
        int c = g_cellof[i];
        int p = atomicAdd(&g_ccur[c], 1);
        g_pts[p] = make_float4(x, y, z, fmaf(x, x, fmaf(y, y, z * z)));
        g_flw[p] = make_float4(flw[3 * i + 0], flw[3 * i + 1], flw[3 * i + 2], 0.f);
    } else if (i < M + N) {
        int j = i - M;
        float x = qp[3 * j + 0];
        float y = qp[3 * j + 1];
        float z = qp[3 * j + 2];
        int c = g_qcell[j];
        int p = atomicAdd(&g_qcur[c], 1);
        g_qs[p] = make_float4(x, y, z, fmaf(x, x, fmaf(y, y, z * z)));
        g_qid[p] = j;
    }
}

// IDW over positions (flow pre-gathered into grid order).
__device__ __forceinline__ void idw_store(
    float* __restrict__ out, int qi, float q2, const float* bd, const int* bi)
{
    float wsum = 0.f, ox = 0.f, oy = 0.f, oz = 0.f;
#pragma unroll
    for (int k = 0; k < KNN; ++k) {
        float d2 = fmaxf(q2 + bd[k], 0.0f);
        float w = 1.0f / (d2 + 1e-8f);
        float4 fv = g_flw[bi[k]];
        ox = fmaf(w, fv.x, ox);
        oy = fmaf(w, fv.y, oy);
        oz = fmaf(w, fv.z, oz);
        wsum += w;
    }
    float inv = 1.0f / wsum;
    out[3 * qi + 0] = ox * inv;
    out[3 * qi + 1] = oy * inv;
    out[3 * qi + 2] = oz * inv;
}

// Phase A: per-thread; box l<=1 then shell l=2; batch-4 scans for MLP.
__global__ void __launch_bounds__(128) knn_easy_kernel(
    float* __restrict__ out, int N)
{
    int tq = blockIdx.x * blockDim.x + threadIdx.x;
    if (tq >= N) return;

    float4 qv = g_qs[tq];
    const float nqx = -2.0f * qv.x;
    const float nqy = -2.0f * qv.y;
    const float nqz = -2.0f * qv.z;
    const float q2 = qv.w;
    const float hmin = g_bb[6];

    int cx = (int)((qv.x - g_bb[0]) * g_bb[3]);
    int cy = (int)((qv.y - g_bb[1]) * g_bb[4]);
    int cz = (int)((qv.z - g_bb[2]) * g_bb[5]);
    cx = min(G - 1, max(0, cx));
    cy = min(G - 1, max(0, cy));
    cz = min(G - 1, max(0, cz));

    float bd[KNN];
    int   bi[KNN];
#pragma unroll
    for (int k = 0; k < KNN; ++k) { bd[k] = CUDART_INF_F; bi[k] = 0; }

    auto ins = [&](float sc, int p) {
        if (sc < bd[KNN - 1]) {
            bd[KNN - 1] = sc;
            bi[KNN - 1] = p;          // position; no sid indirection
#pragma unroll
            for (int k = KNN - 1; k > 0; --k) {
                if (bd[k] < bd[k - 1]) {
                    float td = bd[k]; bd[k] = bd[k - 1]; bd[k - 1] = td;
                    int   ti = bi[k]; bi[k] = bi[k - 1]; bi[k - 1] = ti;
                }
            }
        }
    };

    auto do_row = [&](int z, int y, int x0, int x1) {
        if ((unsigned)z >= G || (unsigned)y >= G) return;
        x0 = max(x0, 0);
        x1 = min(x1, G - 1);
        if (x0 > x1) return;
        int rb = (z * G + y) * G;
        int p = g_cstart[rb + x0];
        int e = g_cstart[rb + x1 + 1];
        for (; p + 4 <= e; p += 4) {
            float4 r0 = g_pts[p + 0];
            float4 r1 = g_pts[p + 1];
            float4 r2 = g_pts[p + 2];
            float4 r3 = g_pts[p + 3];
            float s0 = fmaf(r0.x, nqx, fmaf(r0.y, nqy, fmaf(r0.z, nqz, r0.w)));
            float s1 = fmaf(r1.x, nqx, fmaf(r1.y, nqy, fmaf(r1.z, nqz, r1.w)));
            float s2 = fmaf(r2.x, nqx, fmaf(r2.y, nqy, fmaf(r2.z, nqz, r2.w)));
            float s3 = fmaf(r3.x, nqx, fmaf(r3.y, nqy, fmaf(r3.z, nqz, r3.w)));
            float m = fminf(fminf(s0, s1), fminf(s2, s3));
            if (m < bd[KNN - 1]) {
                ins(s0, p); ins(s1, p + 1); ins(s2, p + 2); ins(s3, p + 3);
            }
        }
        for (; p < e; ++p) {
            float4 r = g_pts[p];
            float sc = fmaf(r.x, nqx, fmaf(r.y, nqy, fmaf(r.z, nqz, r.w)));
            ins(sc, p);
        }
    };

    // Box l<=1 (bound after l=0 can never fire, so scan it as one box).
    for (int dz = -1; dz <= 1; ++dz)
        for (int dy = -1; dy <= 1; ++dy)
            do_row(cz + dz, cy + dy, cx - 1, cx + 1);

    bool done = (q2 + bd[KNN - 1] < hmin * hmin - 0.05f);
    if (!done) {
        // Shell l=2.
        for (int dy = -2; dy <= 2; ++dy) {
            do_row(cz - 2, cy + dy, cx - 2, cx + 2);
            do_row(cz + 2, cy + dy, cx - 2, cx + 2);
        }
        for (int dz = -1; dz <= 1; ++dz) {
            do_row(cz + dz, cy - 2, cx - 2, cx + 2);
            do_row(cz + dz, cy + 2, cx - 2, cx + 2);
            for (int dy = -1; dy <= 1; ++dy) {
                do_row(cz + dz, cy + dy, cx - 2, cx - 2);
                do_row(cz + dz, cy + dy, cx + 2, cx + 2);
            }
        }
        float bound = 2.0f * hmin;
        done = (q2 + bd[KNN - 1] < bound * bound - 0.05f);
    }

    if (done) {
        idw_store(out, g_qid[tq], q2, bd, bi);
    } else {
        int slot = atomicAdd(&g_hardcnt, 1);
        g_hard[slot] = tq;
    }
}

// Phase B: one warp per hard query; lanes split shell rows. Per-shell stop uses
// a 5-shfl warp-min of lane 8ths (>= union 8th -> conservative, exact). One
// full merge at the end.
__global__ void __launch_bounds__(256) knn_hard_kernel(float* __restrict__ out)
{
    __shared__ float sdist[8][32 * KNN];
    __shared__ int   sidx[8][32 * KNN];

    int lane = threadIdx.x & 31;
    int wslot = threadIdx.x >> 5;
    int wgid = (blockIdx.x * blockDim.x + threadIdx.x) >> 5;
    int nwarps = (gridDim.x * blockDim.x) >> 5;
    int hcnt = g_hardcnt;
    const float hmin = g_bb[6];

    for (int h = wgid; h < hcnt; h += nwarps) {
        int tq = g_hard[h];
        float4 qv = g_qs[tq];
        const float nqx = -2.0f * qv.x;
        const float nqy = -2.0f * qv.y;
        const float nqz = -2.0f * qv.z;
        const float q2 = qv.w;

        int cx = (int)((qv.x - g_bb[0]) * g_bb[3]);
        int cy = (int)((qv.y - g_bb[1]) * g_bb[4]);
        int cz = (int)((qv.z - g_bb[2]) * g_bb[5]);
        cx = min(G - 1, max(0, cx));
        cy = min(G - 1, max(0, cy));
        cz = min(G - 1, max(0, cz));

        float bd[KNN];
        int   bi[KNN];
#pragma unroll
        for (int k = 0; k < KNN; ++k) { bd[k] = CUDART_INF_F; bi[k] = 0; }

        auto ins = [&](float sc, int p) {
            if (sc < bd[KNN - 1]) {
                bd[KNN - 1] = sc;
                bi[KNN - 1] = p;
#pragma unroll
                for (int k = KNN - 1; k > 0; --k) {
                    if (bd[k] < bd[k - 1]) {
                        float td = bd[k]; bd[k] = bd[k - 1]; bd[k - 1] = td;
                        int   ti = bi[k]; bi[k] = bi[k - 1]; bi[k - 1] = ti;
                    }
                }
            }
        };

        auto scan_run = [&](int z, int y, int x0, int x1) {
            if ((unsigned)z >= G || (unsigned)y >= G) return;
            x0 = max(x0, 0);
            x1 = min(x1, G - 1);
            if (x0 > x1) return;
            int rb = (z * G + y) * G;
            int p = g_cstart[rb + x0];
            int e = g_cstart[rb + x1 + 1];
            for (; p + 4 <= e; p += 4) {
                float4 r0 = g_pts[p + 0];
                float4 r1 = g_pts[p + 1];
                float4 r2 = g_pts[p + 2];
                float4 r3 = g_pts[p + 3];
                float s0 = fmaf(r0.x, nqx, fmaf(r0.y, nqy, fmaf(r0.z, nqz, r0.w)));
                float s1 = fmaf(r1.x, nqx, fmaf(r1.y, nqy, fmaf(r1.z, nqz, r1.w)));
                float s2 = fmaf(r2.x, nqx, fmaf(r2.y, nqy, fmaf(r2.z, nqz, r2.w)));
                float s3 = fmaf(r3.x, nqx, fmaf(r3.y, nqy, fmaf(r3.z, nqz, r3.w)));
                float m = fminf(fminf(s0, s1), fminf(s2, s3));
                if (m < bd[KNN - 1]) {
                    ins(s0, p); ins(s1, p + 1); ins(s2, p + 2); ins(s3, p + 3);
                }
            }
            for (; p < e; ++p) {
                float4 r = g_pts[p];
                float sc = fmaf(r.x, nqx, fmaf(r.y, nqy, fmaf(r.z, nqz, r.w)));
                ins(sc, p);
            }
        };

        for (int l = 0; l < G; ++l) {
            int side = 2 * l + 1;
            int pairs = side * side;
            for (int pr = lane; pr < pairs; pr += 32) {
                int dz = pr / side - l;
                int dy = pr % side - l;
                int z = cz + dz, y = cy + dy;
                if (abs(dz) == l || abs(dy) == l) {
                    scan_run(z, y, cx - l, cx + l);
                } else {
                    scan_run(z, y, cx - l, cx - l);
                    scan_run(z, y, cx + l, cx + l);
                }
            }
            __syncwarp();
            // Conservative stop: warp-min of lane 8ths >= union 8th.
            float kmin = bd[KNN - 1];
#pragma unroll
            for (int off = 16; off > 0; off >>= 1)
                kmin = fminf(kmin, __shfl_xor_sync(0xffffffffu, kmin, off));
            float bound = (float)l * hmin;
            if (q2 + kmin < bound * bound - 0.05f) break;
        }

        // Single exact final merge of all lanes' lists (disjoint candidate sets).
        __syncwarp();
#pragma unroll
        for (int k = 0; k < KNN; ++k) {
            sdist[wslot][lane * KNN + k] = bd[k];
            sidx[wslot][lane * KNN + k] = bi[k];
        }
        __syncwarp();
        if (lane == 0) {
            float md[KNN];
            int   mi[KNN];
#pragma unroll
            for (int k = 0; k < KNN; ++k) { md[k] = CUDART_INF_F; mi[k] = 0; }
            for (int e = 0; e < 32 * KNN; ++e) {
                float v = sdist[wslot][e];
                if (v < md[KNN - 1]) {
                    md[KNN - 1] = v;
                    mi[KNN - 1] = sidx[wslot][e];
#pragma unroll
                    for (int k = KNN - 1; k > 0; --k) {
                        if (md[k] < md[k - 1]) {
                            float td = md[k]; md[k] = md[k - 1]; md[k - 1] = td;
                            int   ti = mi[k]; mi[k] = mi[k - 1]; mi[k - 1] = ti;
                        }
                    }
                }
            }
            idw_store(out, g_qid[tq], q2, md, mi);
        }
        __syncwarp();
    }
}

extern "C" void kernel_launch(void* const* d_in, const int* in_sizes, int n_in,
                              void* d_out, int out_size) {
    const float* q = (const float*)d_in[0];
    const float* r = (const float*)d_in[1];
    const float* f = (const float*)d_in[2];
    int N = in_sizes[0] / 3;
    int M = in_sizes[1] / 3;
    if (M > MMAX) M = MMAX;
    if (N > NMAX) N = NMAX;

    init_kernel<<<NCELL / 256, 256>>>();
    bbox_kernel<<<64, 256>>>(r, M);
    hist_kernel<<<(M + N + 255) / 256, 256>>>(r, q, M, N);
    scan1_kernel<<<2 * NCHUNK, 256>>>();
    scan2_kernel<<<2 * NCHUNK, 256>>>(M, N);
    scatter_kernel<<<(M + N + 255) / 256, 256>>>(r, q, f, M, N);
    knn_easy_kernel<<<(N + 127) / 128, 128>>>((float*)d_out, N);
    knn_hard_kernel<<<128, 256>>>((float*)d_out);
}

// round 17
// speedup vs baseline: 1.5756x; 1.5664x over previous
#include <cuda_runtime.h>
#include <math_constants.h>

// Exact 8-NN IDW flow interpolation: uniform grid + expanding shells.
// Phase A: per-thread; box l<=1 then shell l=2; batch-4 scans; bi[] holds grid
// POSITIONS (flow pre-gathered into grid order -> no sid indirection).
// Phase B: warp-per-query tail; per-shell EXACT union-kth via 8-step
// heads-of-sorted-lists warp pop; single final merge.
// Inputs: query_points [N,3] f32, ref_points [M,3] f32, ref_flow [M,3] f32 ; out [N,3] f32

#define NMAX  32768
#define MMAX  16384
#define KNN   8
#define G     32
#define NCELL (G * G * G)
#define CHUNK 512
#define NCHUNK (NCELL / CHUNK)   // 64

__device__ float4 g_pts[MMAX];         // grid-sorted refs: (x, y, z, |r|^2)
__device__ float4 g_flw[MMAX];         // grid-sorted flow
__device__ int    g_cstart[NCELL + 1];
__device__ int    g_ccnt[NCELL];
__device__ int    g_ccur[NCELL];
__device__ int    g_cellof[MMAX];
__device__ int    g_qcnt[NCELL];
__device__ int    g_qcur[NCELL];
__device__ int    g_qcell[NMAX];
__device__ float4 g_qs[NMAX];          // cell-sorted query coords (x,y,z,|q|^2)
__device__ int    g_qid[NMAX];         // sorted slot -> original query index
__device__ int    g_hard[NMAX];
__device__ int    g_hardcnt;
__device__ float  g_bb[8];             // [0..2]=min, [3..5]=1/h, [6]=hmin
__device__ int    g_bsum[2 * NCHUNK];
__device__ unsigned g_bbmin[3], g_bbmax[3];
__device__ int    g_bbdone;

__device__ __forceinline__ unsigned f2key(float f) {
    unsigned b = __float_as_uint(f);
    return b ^ ((b & 0x80000000u) ? 0xFFFFFFFFu : 0x80000000u);
}
__device__ __forceinline__ float key2f(unsigned k) {
    unsigned b = (k & 0x80000000u) ? (k ^ 0x80000000u) : ~k;
    return __uint_as_float(b);
}

__global__ void init_kernel() {
    int i = blockIdx.x * blockDim.x + threadIdx.x;
    if (i < NCELL) { g_ccnt[i] = 0; g_qcnt[i] = 0; }
    if (i == 0) {
        g_hardcnt = 0;
        g_bbdone = 0;
#pragma unroll
        for (int a = 0; a < 3; ++a) { g_bbmin[a] = 0xFFFFFFFFu; g_bbmax[a] = 0u; }
    }
}

__global__ void __launch_bounds__(256) bbox_kernel(const float* __restrict__ ref, int M) {
    __shared__ float smn[3][8], smx[3][8];
    int t = threadIdx.x, lane = t & 31, wid = t >> 5;
    float mn[3] = {CUDART_INF_F, CUDART_INF_F, CUDART_INF_F};
    float mx[3] = {-CUDART_INF_F, -CUDART_INF_F, -CUDART_INF_F};
    for (int i = blockIdx.x * blockDim.x + t; i < M; i += gridDim.x * blockDim.x) {
#pragma unroll
        for (int a = 0; a < 3; ++a) {
            float v = ref[3 * i + a];
            mn[a] = fminf(mn[a], v);
            mx[a] = fmaxf(mx[a], v);
        }
    }
#pragma unroll
    for (int off = 16; off > 0; off >>= 1) {
#pragma unroll
        for (int a = 0; a < 3; ++a) {
            mn[a] = fminf(mn[a], __shfl_xor_sync(0xffffffffu, mn[a], off));
            mx[a] = fmaxf(mx[a], __shfl_xor_sync(0xffffffffu, mx[a], off));
        }
    }
    if (lane == 0) {
#pragma unroll
        for (int a = 0; a < 3; ++a) { smn[a][wid] = mn[a]; smx[a][wid] = mx[a]; }
    }
    __syncthreads();
    if (t == 0) {
#pragma unroll
        for (int a = 0; a < 3; ++a) {
            float bmn = smn[a][0], bmx = smx[a][0];
            for (int w = 1; w < 8; ++w) {
                bmn = fminf(bmn, smn[a][w]);
                bmx = fmaxf(bmx, smx[a][w]);
            }
            atomicMin(&g_bbmin[a], f2key(bmn));
            atomicMax(&g_bbmax[a], f2key(bmx));
        }
        __threadfence();
        int done = atomicAdd(&g_bbdone, 1);
        if (done == gridDim.x - 1) {
            float hmin = CUDART_INF_F;
#pragma unroll
            for (int a = 0; a < 3; ++a) {
                float lo = key2f(g_bbmin[a]) - 1e-4f;
                float hi = key2f(g_bbmax[a]) + 1e-4f;
                float h = fmaxf((hi - lo) / (float)G, 1e-6f);
                g_bb[a] = lo;
                g_bb[3 + a] = 1.0f / h;
                hmin = fminf(hmin, h);
            }
            g_bb[6] = hmin;
        }
    }
}

__device__ __forceinline__ int cell_of(float x, float y, float z) {
    int cx = (int)((x - g_bb[0]) * g_bb[3]);
    int cy = (int)((y - g_bb[1]) * g_bb[4]);
    int cz = (int)((z - g_bb[2]) * g_bb[5]);
    cx = min(G - 1, max(0, cx));
    cy = min(G - 1, max(0, cy));
    cz = min(G - 1, max(0, cz));
    return (cz * G + cy) * G + cx;
}

__global__ void hist_kernel(const float* __restrict__ ref,
                            const float* __restrict__ qp, int M, int N) {
    int i = blockIdx.x * blockDim.x + threadIdx.x;
    if (i < M) {
        int c = cell_of(ref[3 * i + 0], ref[3 * i + 1], ref[3 * i + 2]);
        g_cellof[i] = c;
        atomicAdd(&g_ccnt[c], 1);
    } else if (i < M + N) {
        int j = i - M;
        int c = cell_of(qp[3 * j + 0], qp[3 * j + 1], qp[3 * j + 2]);
        g_qcell[j] = c;
        atomicAdd(&g_qcnt[c], 1);
    }
}

__global__ void __launch_bounds__(256) scan1_kernel() {
    __shared__ int wsum[8];
    int b = blockIdx.x;
    const int* cnt = (b < NCHUNK) ? g_ccnt : g_qcnt;
    int c0 = (b & (NCHUNK - 1)) * CHUNK;
    int t = threadIdx.x, lane = t & 31, wid = t >> 5;
    int2 v = *(const int2*)&cnt[c0 + 2 * t];
    int s = v.x + v.y;
#pragma unroll
    for (int off = 16; off > 0; off >>= 1)
        s += __shfl_xor_sync(0xffffffffu, s, off);
    if (lane == 0) wsum[wid] = s;
    __syncthreads();
    if (t == 0) {
        int tot = 0;
#pragma unroll
        for (int w = 0; w < 8; ++w) tot += wsum[w];
        g_bsum[b] = tot;
    }
}

__global__ void __launch_bounds__(256) scan2_kernel(int M, int N) {
    __shared__ int wsum[8];
    __shared__ int chunk_off;
    int b = blockIdx.x;
    bool isq = (b >= NCHUNK);
    const int* cnt = isq ? g_qcnt : g_ccnt;
    int t = threadIdx.x, lane = t & 31, wid = t >> 5;

    if (wid == 0) {
        int base = (isq ? NCHUNK : 0);
        int v0 = g_bsum[base + 2 * lane];
        int v1 = g_bsum[base + 2 * lane + 1];
        int s = v0 + v1;
        int inc = s;
#pragma unroll
        for (int off = 1; off < 32; off <<= 1) {
            int u = __shfl_up_sync(0xffffffffu, inc, off);
            if (lane >= off) inc += u;
        }
        int ex = inc - s;
        int myc = b & (NCHUNK - 1);
        int want0 = myc >> 1;
        int sel = __shfl_sync(0xffffffffu, ex, want0);
        int selv0 = __shfl_sync(0xffffffffu, v0, want0);
        if (lane == 0) chunk_off = (myc & 1) ? (sel + selv0) : sel;
    }
    __syncthreads();

    const int c0 = (b & (NCHUNK - 1)) * CHUNK;
    int2 v = *(const int2*)&cnt[c0 + 2 * t];
    int s = v.x + v.y;
    int inc = s;
#pragma unroll
    for (int off = 1; off < 32; off <<= 1) {
        int u = __shfl_up_sync(0xffffffffu, inc, off);
        if (lane >= off) inc += u;
    }
    if (lane == 31) wsum[wid] = inc;
    __syncthreads();
    if (wid == 0 && lane < 8) {
        int w = wsum[lane];
#pragma unroll
        for (int off = 1; off < 8; off <<= 1) {
            int u = __shfl_up_sync(0xffu, w, off);
            if (lane >= off) w += u;
        }
        wsum[lane] = w;
    }
    __syncthreads();
    int ex = inc - s + (wid ? wsum[wid - 1] : 0) + chunk_off;
    int2 st = make_int2(ex, ex + v.x);
    if (isq) {
        *(int2*)&g_qcur[c0 + 2 * t] = st;
    } else {
        *(int2*)&g_cstart[c0 + 2 * t] = st;
        *(int2*)&g_ccur[c0 + 2 * t] = st;
    }
    if (!isq && b == 0 && t == 0) g_cstart[NCELL] = M;
}

__global__ void scatter_kernel(const float* __restrict__ ref,
                               const float* __restrict__ qp,
                               const float* __restrict__ flw, int M, int N) {
    int i = blockIdx.x * blockDim.x + threadIdx.x;
    if (i < M) {
        float x = ref[3 * i + 0];
        float y = ref[3 * i + 1];
        float z = ref[3 * i + 2];
        int c = g_cellof[i];
        int p = atomicAdd(&g_ccur[c], 1);
        g_pts[p] = make_float4(x, y, z, fmaf(x, x, fmaf(y, y, z * z)));
        g_flw[p] = make_float4(flw[3 * i + 0], flw[3 * i + 1], flw[3 * i + 2], 0.f);
    } else if (i < M + N) {
        int j = i - M;
        float x = qp[3 * j + 0];
        float y = qp[3 * j + 1];
        float z = qp[3 * j + 2];
        int c = g_qcell[j];
        int p = atomicAdd(&g_qcur[c], 1);
        g_qs[p] = make_float4(x, y, z, fmaf(x, x, fmaf(y, y, z * z)));
        g_qid[p] = j;
    }
}

__device__ __forceinline__ void idw_store(
    float* __restrict__ out, int qi, float q2, const float* bd, const int* bi)
{
    float wsum = 0.f, ox = 0.f, oy = 0.f, oz = 0.f;
#pragma unroll
    for (int k = 0; k < KNN; ++k) {
        float d2 = fmaxf(q2 + bd[k], 0.0f);
        float w = 1.0f / (d2 + 1e-8f);
        float4 fv = g_flw[bi[k]];
        ox = fmaf(w, fv.x, ox);
        oy = fmaf(w, fv.y, oy);
        oz = fmaf(w, fv.z, oz);
        wsum += w;
    }
    float inv = 1.0f / wsum;
    out[3 * qi + 0] = ox * inv;
    out[3 * qi + 1] = oy * inv;
    out[3 * qi + 2] = oz * inv;
}

// Phase A: per-thread; box l<=1 then shell l=2; batch-4 scans for MLP.
__global__ void __launch_bounds__(128) knn_easy_kernel(
    float* __restrict__ out, int N)
{
    int tq = blockIdx.x * blockDim.x + threadIdx.x;
    if (tq >= N) return;

    float4 qv = g_qs[tq];
    const float nqx = -2.0f * qv.x;
    const float nqy = -2.0f * qv.y;
    const float nqz = -2.0f * qv.z;
    const float q2 = qv.w;
    const float hmin = g_bb[6];

    int cx = (int)((qv.x - g_bb[0]) * g_bb[3]);
    int cy = (int)((qv.y - g_bb[1]) * g_bb[4]);
    int cz = (int)((qv.z - g_bb[2]) * g_bb[5]);
    cx = min(G - 1, max(0, cx));
    cy = min(G - 1, max(0, cy));
    cz = min(G - 1, max(0, cz));

    float bd[KNN];
    int   bi[KNN];
#pragma unroll
    for (int k = 0; k < KNN; ++k) { bd[k] = CUDART_INF_F; bi[k] = 0; }

    auto ins = [&](float sc, int p) {
        if (sc < bd[KNN - 1]) {
            bd[KNN - 1] = sc;
            bi[KNN - 1] = p;
#pragma unroll
            for (int k = KNN - 1; k > 0; --k) {
                if (bd[k] < bd[k - 1]) {
                    float td = bd[k]; bd[k] = bd[k - 1]; bd[k - 1] = td;
                    int   ti = bi[k]; bi[k] = bi[k - 1]; bi[k - 1] = ti;
                }
            }
        }
    };

    auto do_row = [&](int z, int y, int x0, int x1) {
        if ((unsigned)z >= G || (unsigned)y >= G) return;
        x0 = max(x0, 0);
        x1 = min(x1, G - 1);
        if (x0 > x1) return;
        int rb = (z * G + y) * G;
        int p = g_cstart[rb + x0];
        int e = g_cstart[rb + x1 + 1];
        for (; p + 4 <= e; p += 4) {
            float4 r0 = g_pts[p + 0];
            float4 r1 = g_pts[p + 1];
            float4 r2 = g_pts[p + 2];
            float4 r3 = g_pts[p + 3];
            float s0 = fmaf(r0.x, nqx, fmaf(r0.y, nqy, fmaf(r0.z, nqz, r0.w)));
            float s1 = fmaf(r1.x, nqx, fmaf(r1.y, nqy, fmaf(r1.z, nqz, r1.w)));
            float s2 = fmaf(r2.x, nqx, fmaf(r2.y, nqy, fmaf(r2.z, nqz, r2.w)));
            float s3 = fmaf(r3.x, nqx, fmaf(r3.y, nqy, fmaf(r3.z, nqz, r3.w)));
            float m = fminf(fminf(s0, s1), fminf(s2, s3));
            if (m < bd[KNN - 1]) {
                ins(s0, p); ins(s1, p + 1); ins(s2, p + 2); ins(s3, p + 3);
            }
        }
        for (; p < e; ++p) {
            float4 r = g_pts[p];
            float sc = fmaf(r.x, nqx, fmaf(r.y, nqy, fmaf(r.z, nqz, r.w)));
            ins(sc, p);
        }
    };

    // Box l<=1 (bound after l=0 can never fire, so scan it as one box).
    for (int dz = -1; dz <= 1; ++dz)
        for (int dy = -1; dy <= 1; ++dy)
            do_row(cz + dz, cy + dy, cx - 1, cx + 1);

    bool done = (q2 + bd[KNN - 1] < hmin * hmin - 0.05f);
    if (!done) {
        // Shell l=2.
        for (int dy = -2; dy <= 2; ++dy) {
            do_row(cz - 2, cy + dy, cx - 2, cx + 2);
            do_row(cz + 2, cy + dy, cx - 2, cx + 2);
        }
        for (int dz = -1; dz <= 1; ++dz) {
            do_row(cz + dz, cy - 2, cx - 2, cx + 2);
            do_row(cz + dz, cy + 2, cx - 2, cx + 2);
            for (int dy = -1; dy <= 1; ++dy) {
                do_row(cz + dz, cy + dy, cx - 2, cx - 2);
                do_row(cz + dz, cy + dy, cx + 2, cx + 2);
            }
        }
        float bound = 2.0f * hmin;
        done = (q2 + bd[KNN - 1] < bound * bound - 0.05f);
    }

    if (done) {
        idw_store(out, g_qid[tq], q2, bd, bi);
    } else {
        int slot = atomicAdd(&g_hardcnt, 1);
        g_hard[slot] = tq;
    }
}

// Phase B: one warp per hard query; lanes split shell rows. Per-shell EXACT
// union-kth via 8-step heads-of-sorted-lists warp pop (~70 inst). One final
// full merge feeds IDW.
__global__ void __launch_bounds__(256) knn_hard_kernel(float* __restrict__ out)
{
    __shared__ float sdist[8][32 * KNN];
    __shared__ int   sidx[8][32 * KNN];

    int lane = threadIdx.x & 31;
    int wslot = threadIdx.x >> 5;
    int wgid = (blockIdx.x * blockDim.x + threadIdx.x) >> 5;
    int nwarps = (gridDim.x * blockDim.x) >> 5;
    int hcnt = g_hardcnt;
    const float hmin = g_bb[6];

    for (int h = wgid; h < hcnt; h += nwarps) {
        int tq = g_hard[h];
        float4 qv = g_qs[tq];
        const float nqx = -2.0f * qv.x;
        const float nqy = -2.0f * qv.y;
        const float nqz = -2.0f * qv.z;
        const float q2 = qv.w;

        int cx = (int)((qv.x - g_bb[0]) * g_bb[3]);
        int cy = (int)((qv.y - g_bb[1]) * g_bb[4]);
        int cz = (int)((qv.z - g_bb[2]) * g_bb[5]);
        cx = min(G - 1, max(0, cx));
        cy = min(G - 1, max(0, cy));
        cz = min(G - 1, max(0, cz));

        float bd[KNN];
        int   bi[KNN];
#pragma unroll
        for (int k = 0; k < KNN; ++k) { bd[k] = CUDART_INF_F; bi[k] = 0; }

        auto ins = [&](float sc, int p) {
            if (sc < bd[KNN - 1]) {
                bd[KNN - 1] = sc;
                bi[KNN - 1] = p;
#pragma unroll
                for (int k = KNN - 1; k > 0; --k) {
                    if (bd[k] < bd[k - 1]) {
                        float td = bd[k]; bd[k] = bd[k - 1]; bd[k - 1] = td;
                        int   ti = bi[k]; bi[k] = bi[k - 1]; bi[k - 1] = ti;
                    }
                }
            }
        };

        auto scan_run = [&](int z, int y, int x0, int x1) {
            if ((unsigned)z >= G || (unsigned)y >= G) return;
            x0 = max(x0, 0);
            x1 = min(x1, G - 1);
            if (x0 > x1) return;
            int rb = (z * G + y) * G;
            int p = g_cstart[rb + x0];
            int e = g_cstart[rb + x1 + 1];
            for (; p + 4 <= e; p += 4) {
                float4 r0 = g_pts[p + 0];
                float4 r1 = g_pts[p + 1];
                float4 r2 = g_pts[p + 2];
                float4 r3 = g_pts[p + 3];
                float s0 = fmaf(r0.x, nqx, fmaf(r0.y, nqy, fmaf(r0.z, nqz, r0.w)));
                float s1 = fmaf(r1.x, nqx, fmaf(r1.y, nqy, fmaf(r1.z, nqz, r1.w)));
                float s2 = fmaf(r2.x, nqx, fmaf(r2.y, nqy, fmaf(r2.z, nqz, r2.w)));
                float s3 = fmaf(r3.x, nqx, fmaf(r3.y, nqy, fmaf(r3.z, nqz, r3.w)));
                float m = fminf(fminf(s0, s1), fminf(s2, s3));
                if (m < bd[KNN - 1]) {
                    ins(s0, p); ins(s1, p + 1); ins(s2, p + 2); ins(s3, p + 3);
                }
            }
            for (; p < e; ++p) {
                float4 r = g_pts[p];
                float sc = fmaf(r.x, nqx, fmaf(r.y, nqy, fmaf(r.z, nqz, r.w)));
                ins(sc, p);
            }
        };

        for (int l = 0; l < G; ++l) {
            int side = 2 * l + 1;
            int pairs = side * side;
            for (int pr = lane; pr < pairs; pr += 32) {
                int dz = pr / side - l;
                int dy = pr % side - l;
                int z = cz + dz, y = cy + dy;
                if (abs(dz) == l || abs(dy) == l) {
                    scan_run(z, y, cx - l, cx + l);
                } else {
                    scan_run(z, y, cx - l, cx - l);
                    scan_run(z, y, cx + l, cx + l);
                }
            }
            __syncwarp();
            // EXACT union-kth: 8 pops of warp-min over sorted-list heads.
            float kth = CUDART_INF_F;
            {
                int ci = 0;
#pragma unroll
                for (int it = 0; it < KNN; ++it) {
                    float head = (ci < KNN) ? bd[ci] : CUDART_INF_F;
                    float m = head;
#pragma unroll
                    for (int off = 16; off > 0; off >>= 1)
                        m = fminf(m, __shfl_xor_sync(0xffffffffu, m, off));
                    unsigned own = __ballot_sync(0xffffffffu,
                                                 head == m && ci < KNN);
                    if (own != 0u && lane == (__ffs(own) - 1)) ci++;
                    kth = m;   // after 8 iterations: exact union 8th-smallest
                }
            }
            float bound = (float)l * hmin;
            if (q2 + kth < bound * bound - 0.05f) break;
        }

        // Single exact final merge of all lanes' lists (disjoint candidate sets).
        __syncwarp();
#pragma unroll
        for (int k = 0; k < KNN; ++k) {
            sdist[wslot][lane * KNN + k] = bd[k];
            sidx[wslot][lane * KNN + k] = bi[k];
        }
        __syncwarp();
        if (lane == 0) {
            float md[KNN];
            int   mi[KNN];
#pragma unroll
            for (int k = 0; k < KNN; ++k) { md[k] = CUDART_INF_F; mi[k] = 0; }
            for (int e = 0; e < 32 * KNN; ++e) {
                float v = sdist[wslot][e];
                if (v < md[KNN - 1]) {
                    md[KNN - 1] = v;
                    mi[KNN - 1] = sidx[wslot][e];
#pragma unroll
                    for (int k = KNN - 1; k > 0; --k) {
                        if (md[k] < md[k - 1]) {
                            float td = md[k]; md[k] = md[k - 1]; md[k - 1] = td;
                            int   ti = mi[k]; mi[k] = mi[k - 1]; mi[k - 1] = ti;
                        }
                    }
                }
            }
            idw_store(out, g_qid[tq], q2, md, mi);
        }
        __syncwarp();
    }
}

extern "C" void kernel_launch(void* const* d_in, const int* in_sizes, int n_in,
                              void* d_out, int out_size) {
    const float* q = (const float*)d_in[0];
    const float* r = (const float*)d_in[1];
    const float* f = (const float*)d_in[2];
    int N = in_sizes[0] / 3;
    int M = in_sizes[1] / 3;
    if (M > MMAX) M = MMAX;
    if (N > NMAX) N = NMAX;

    init_kernel<<<NCELL / 256, 256>>>();
    bbox_kernel<<<64, 256>>>(r, M);
    hist_kernel<<<(M + N + 255) / 256, 256>>>(r, q, M, N);
    scan1_kernel<<<2 * NCHUNK, 256>>>();
    scan2_kernel<<<2 * NCHUNK, 256>>>(M, N);
    scatter_kernel<<<(M + N + 255) / 256, 256>>>(r, q, f, M, N);
    knn_easy_kernel<<<(N + 127) / 128, 128>>>((float*)d_out, N);
    knn_hard_kernel<<<128, 256>>>((float*)d_out);
}